// round 7
// baseline (speedup 1.0000x reference)
#include <cuda_runtime.h>
#include <cuda_fp16.h>
#include <math.h>
#include <stdint.h>

// Problem dims
constexpr int kT  = 4096;   // timesteps
constexpr int kD  = 1024;   // input dim
constexpr int kH  = 2048;   // hidden
constexpr int kH3 = 3 * kH; // 6144

// GRU kernel: 448 threads (14 warps), 32 j per block, 96 rows (j-major: lr = lj*3+gate)
// rows lr<54 in smem (18 j), rows 54..95 in registers (3 per warp).
constexpr int GRU_THREADS = 448;
constexpr int SMEM_ROWS = 54;
constexpr int SMEM_H   = kH * 2;                       // 4096 B
constexpr int SMEM_W   = SMEM_ROWS * kH * 2;           // 221184 B
constexpr int SMEM_PRE = 96 * 4;                       // 384 B
constexpr int GRU_SMEM = SMEM_H + SMEM_W + SMEM_PRE;   // 225664 B

// -------- scratch (static device globals; no allocation allowed) --------
__device__ float  g_xp[2][(size_t)kT * kH3];    // input projections (fp32)
__device__ __half g_w16[2][(size_t)kH3 * kH];   // fp16 W_hh
__device__ __half g_wih16[2][(size_t)kH3 * kD]; // fp16 W_ih
__device__ __half g_x16[2][(size_t)kT * kD];    // fp16 x
__device__ __align__(16) __half g_h16[2][2][kH]; // ping-pong hidden state [buf][gru][H]
__device__ float  g_act[256];                   // fc1 activations
__device__ unsigned g_ctr[2];                   // monotonic barrier counters (reset by gemm)

// ---------------- monotonic-counter grid barrier (64 blocks per GRU) ----------------
__device__ __forceinline__ void bar_sync(int gru, unsigned target)
{
    __syncthreads();
    if (threadIdx.x == 0) {
        __threadfence();                       // release this block's writes
        atomicAdd(&g_ctr[gru], 1u);
        while (*(volatile unsigned*)&g_ctr[gru] < target) {}
        __threadfence();                       // acquire others' writes
    }
    __syncthreads();
}

// ---------------- conversions (fused: 2 launches so gru_seq lands at index 3) --------
__global__ void convert_whh_both(const float* __restrict__ W1, const float* __restrict__ W2)
{
    const size_t i = (size_t)blockIdx.x * blockDim.x + threadIdx.x;   // kH3*kH/2
    const float2* src = (const float2*)(blockIdx.y ? W2 : W1);
    float2 v = src[i];
    ((__half2*)g_w16[blockIdx.y])[i] = __floats2half2_rn(v.x, v.y);
}
__global__ void convert_misc(const float* __restrict__ Wih1, const float* __restrict__ Wih2,
                             const float* __restrict__ x1,   const float* __restrict__ x2)
{
    const size_t i = (size_t)blockIdx.x * blockDim.x + threadIdx.x;
    const int gru = blockIdx.y;
    if (blockIdx.z == 0) {                      // W_ih: kH3*kD/2 elements
        const float2* src = (const float2*)(gru ? Wih2 : Wih1);
        float2 v = src[i];
        ((__half2*)g_wih16[gru])[i] = __floats2half2_rn(v.x, v.y);
    } else {                                    // x: kT*kD/2 elements (guard)
        if (i >= (size_t)kT * kD / 2) return;
        const float2* src = (const float2*)(gru ? x2 : x1);
        float2 v = src[i];
        ((__half2*)g_x16[gru])[i] = __floats2half2_rn(v.x, v.y);
    }
}

// ---------------- Phase A: xp = x @ W_ih^T + b_ih  (fp16 HFMA2) ----------------
constexpr int GBM = 128, GBN = 64, GBK = 32;

__global__ void __launch_bounds__(256, 2) gemm_xp16(
    const float* __restrict__ bih1, const float* __restrict__ bih2)
{
    // reset the gru barrier counters for this launch (runs before gru_seq in-stream)
    if (blockIdx.x == 0 && blockIdx.y == 0 && blockIdx.z == 0 && threadIdx.x == 0) {
        g_ctr[0] = 0; g_ctr[1] = 0;
    }

    const int gru = blockIdx.z;
    const __half* __restrict__ X = g_x16[gru];
    const __half* __restrict__ W = g_wih16[gru];
    const float*  __restrict__ b = gru ? bih2 : bih1;
    float* __restrict__ xp = g_xp[gru];

    __shared__ __half2 As[GBK / 2][GBM + 1];
    __shared__ __half2 Bs[GBK / 2][GBN + 1];

    const int tid = threadIdx.x;
    const int tx = tid & 15, ty = tid >> 4;
    const int t0 = blockIdx.y * GBM;
    const int j0 = blockIdx.x * GBN;

    float acc[8][4] = {};

    for (int k0 = 0; k0 < kD; k0 += GBK) {
        #pragma unroll
        for (int r = 0; r < 2; r++) {
            int i = tid + r * 256;
            int t = i >> 2;
            int kc = (i & 3) * 8;
            uint4 v = *(const uint4*)(X + (size_t)(t0 + t) * kD + k0 + kc);
            const __half2* hv = (const __half2*)&v;
            int k2b = kc >> 1;
            As[k2b + 0][t] = hv[0]; As[k2b + 1][t] = hv[1];
            As[k2b + 2][t] = hv[2]; As[k2b + 3][t] = hv[3];
        }
        {
            int j = tid >> 2;
            int kc = (tid & 3) * 8;
            uint4 v = *(const uint4*)(W + (size_t)(j0 + j) * kD + k0 + kc);
            const __half2* hv = (const __half2*)&v;
            int k2b = kc >> 1;
            Bs[k2b + 0][j] = hv[0]; Bs[k2b + 1][j] = hv[1];
            Bs[k2b + 2][j] = hv[2]; Bs[k2b + 3][j] = hv[3];
        }
        __syncthreads();

        __half2 hz = __float2half2_rn(0.f);
        __half2 hacc[8][4];
        #pragma unroll
        for (int i = 0; i < 8; i++)
            #pragma unroll
            for (int l = 0; l < 4; l++) hacc[i][l] = hz;

        #pragma unroll
        for (int k2 = 0; k2 < GBK / 2; k2++) {
            __half2 a[8], bb[4];
            #pragma unroll
            for (int i = 0; i < 8; i++) a[i] = As[k2][ty * 8 + i];
            #pragma unroll
            for (int l = 0; l < 4; l++) bb[l] = Bs[k2][tx * 4 + l];
            #pragma unroll
            for (int i = 0; i < 8; i++)
                #pragma unroll
                for (int l = 0; l < 4; l++)
                    hacc[i][l] = __hfma2(a[i], bb[l], hacc[i][l]);
        }
        #pragma unroll
        for (int i = 0; i < 8; i++)
            #pragma unroll
            for (int l = 0; l < 4; l++) {
                float2 f = __half22float2(hacc[i][l]);
                acc[i][l] += f.x + f.y;
            }
        __syncthreads();
    }

    const int jj = j0 + tx * 4;
    float4 bv = *(const float4*)(b + jj);
    #pragma unroll
    for (int i = 0; i < 8; i++) {
        float4 v = make_float4(acc[i][0] + bv.x, acc[i][1] + bv.y,
                               acc[i][2] + bv.z, acc[i][3] + bv.w);
        __stcs((float4*)(xp + (size_t)(t0 + ty * 8 + i) * kH3 + jj), v);
    }
}

// ---------------- 8-half dot (fp16 mul-acc, fp32 flush) ----------------
__device__ __forceinline__ float dot8(uint4 wv, uint4 hh)
{
    __half2 t = __hmul2(*(const __half2*)&wv.x, *(const __half2*)&hh.x);
    t = __hfma2(*(const __half2*)&wv.y, *(const __half2*)&hh.y, t);
    t = __hfma2(*(const __half2*)&wv.z, *(const __half2*)&hh.z, t);
    t = __hfma2(*(const __half2*)&wv.w, *(const __half2*)&hh.w, t);
    float2 f = __half22float2(t);
    return f.x + f.y;
}

// ---------------- Phase B: persistent GRU, ALL weights on-chip ----------------
// 128 blocks x 448 threads. Block owns 32 j = 96 rows (lr = local_j*3 + gate).
// Rows lr<54 cached in smem; rows 54..95 live in REGISTERS (3 rows per warp).
// Warp w owns rows {w + 14*i}; w<12: i=0..3 smem + i=4..6 reg; w>=12: i=0..2 smem + i=3..5 reg.
__global__ void __launch_bounds__(GRU_THREADS, 1) gru_seq(
    const float* __restrict__ bhh1, const float* __restrict__ bhh2)
{
    extern __shared__ unsigned char smem_raw[];
    __half* sh_h  = (__half*)smem_raw;                       // 2048 halves
    __half* sh_w  = (__half*)(smem_raw + SMEM_H);            // 54 rows x 2048 halves
    float*  s_pre = (float*)(smem_raw + SMEM_H + SMEM_W);    // 96 row sums

    const int blk = blockIdx.x;       // 0..127
    const int gru = blk >> 6;
    const int jbase = (blk & 63) * 32;
    const float*  __restrict__ bhh = gru ? bhh2 : bhh1;
    const float*  __restrict__ xp  = g_xp[gru];
    const __half* __restrict__ W16 = g_w16[gru];

    const int tid = threadIdx.x;
    const int w = tid >> 5, lane = tid & 31;

    // ---- fill smem rows lr < 54 (dst idx = lr*256 + u) ----
    for (int idx = tid; idx < SMEM_ROWS * 256; idx += GRU_THREADS) {
        int lr = idx >> 8, u = idx & 255;
        int lj = lr / 3, g = lr - 3 * lj;
        ((uint4*)sh_w)[idx] =
            ((const uint4*)(W16 + ((size_t)g * kH + jbase + lj) * kH))[u];
    }

    // ---- preload this warp's 3 register rows ----
    uint4 wreg[3][8];
    const int first_lr = (w < 12) ? (w + 56) : (w + 42);
    #pragma unroll
    for (int s = 0; s < 3; s++) {
        int lr = first_lr + 14 * s;
        int lj = lr / 3, g = lr - 3 * lj;
        const uint4* p = (const uint4*)(W16 + ((size_t)g * kH + jbase + lj) * kH);
        #pragma unroll
        for (int u = 0; u < 8; u++) wreg[s][u] = __ldcg(p + u * 32 + lane);
    }

    if (tid < 32) g_h16[0][gru][jbase + tid] = __float2half(0.f);

    // gate-math threads: warp 12 (tid 384..415), one j per lane
    const bool is_gate = (tid >= 384 && tid < 416);
    const int lj_g = tid & 31;
    const int jg = jbase + lj_g;
    float br = 0.f, bz = 0.f, bn = 0.f, h_prev = 0.f;
    if (is_gate) { br = bhh[jg]; bz = bhh[kH + jg]; bn = bhh[2 * kH + jg]; }

    bar_sync(gru, 64);   // covers smem fill + h0 init across blocks

    const uint4* hv  = (const uint4*)sh_h;
    const uint4* swu = (const uint4*)sh_w;

    for (int t = 0; t < kT; t++) {
        const int cur = t & 1, nxt = cur ^ 1;

        // prefetch xp early (consumed ~1us later)
        float xr = 0.f, xz = 0.f, xn = 0.f;
        if (is_gate) {
            const float* xpt = xp + (size_t)t * kH3;
            xr = __ldcs(xpt + jg);
            xz = __ldcs(xpt + kH + jg);
            xn = __ldcs(xpt + 2 * kH + jg);
        }

        // stage h (256 x uint4)
        if (tid < 256)
            ((uint4*)sh_h)[tid] = ((const uint4*)g_h16[cur][gru])[tid];
        __syncthreads();

        float acc[7] = {0.f, 0.f, 0.f, 0.f, 0.f, 0.f, 0.f};

        if (w < 12) {
            #pragma unroll
            for (int c = 0; c < 4; c++) {               // h chunks of 2 uint4
                uint4 hh0 = hv[(c * 2 + 0) * 32 + lane];
                uint4 hh1 = hv[(c * 2 + 1) * 32 + lane];
                #pragma unroll
                for (int i = 0; i < 4; i++) {           // smem rows w + 14i
                    const uint4* p = swu + (w + 14 * i) * 256;
                    acc[i] += dot8(p[(c * 2 + 0) * 32 + lane], hh0);
                    acc[i] += dot8(p[(c * 2 + 1) * 32 + lane], hh1);
                }
                #pragma unroll
                for (int s = 0; s < 3; s++) {           // reg rows w + 56 + 14s
                    acc[4 + s] += dot8(wreg[s][c * 2 + 0], hh0);
                    acc[4 + s] += dot8(wreg[s][c * 2 + 1], hh1);
                }
            }
        } else {
            #pragma unroll
            for (int c = 0; c < 4; c++) {
                uint4 hh0 = hv[(c * 2 + 0) * 32 + lane];
                uint4 hh1 = hv[(c * 2 + 1) * 32 + lane];
                #pragma unroll
                for (int i = 0; i < 3; i++) {           // smem rows w + 14i
                    const uint4* p = swu + (w + 14 * i) * 256;
                    acc[i] += dot8(p[(c * 2 + 0) * 32 + lane], hh0);
                    acc[i] += dot8(p[(c * 2 + 1) * 32 + lane], hh1);
                }
                #pragma unroll
                for (int s = 0; s < 3; s++) {           // reg rows w + 42 + 14s
                    acc[3 + s] += dot8(wreg[s][c * 2 + 0], hh0);
                    acc[3 + s] += dot8(wreg[s][c * 2 + 1], hh1);
                }
            }
        }

        // butterfly reduce
        #pragma unroll
        for (int off = 16; off; off >>= 1)
            #pragma unroll
            for (int q = 0; q < 7; q++)
                acc[q] += __shfl_xor_sync(0xffffffffu, acc[q], off);

        if (lane == 0) {
            if (w < 12) {
                #pragma unroll
                for (int i = 0; i < 4; i++) s_pre[w + 14 * i] = acc[i];
                #pragma unroll
                for (int s = 0; s < 3; s++) s_pre[w + 56 + 14 * s] = acc[4 + s];
            } else {
                #pragma unroll
                for (int i = 0; i < 3; i++) s_pre[w + 14 * i] = acc[i];
                #pragma unroll
                for (int s = 0; s < 3; s++) s_pre[w + 42 + 14 * s] = acc[3 + s];
            }
        }
        __syncthreads();

        if (is_gate) {
            float hr = s_pre[3 * lj_g + 0] + br;
            float hz = s_pre[3 * lj_g + 1] + bz;
            float hn = s_pre[3 * lj_g + 2] + bn;
            float r = 1.f / (1.f + expf(-(xr + hr)));
            float z = 1.f / (1.f + expf(-(xz + hz)));
            float n = tanhf(xn + r * hn);
            float hnew = (1.f - z) * n + z * h_prev;
            h_prev = hnew;
            g_h16[nxt][gru][jg] = __float2half(hnew);
        }

        bar_sync(gru, 64u * (t + 2));
    }
    // final h in g_h16[0]
}

// ---------------- Phase C1: fc1 (parallel over 32 blocks) ----------------
__global__ void head_fc1(const float* __restrict__ fc1_w, const float* __restrict__ fc1_b)
{
    const int r = blockIdx.x * 8 + (threadIdx.x >> 5);
    const int lane = threadIdx.x & 31;
    const __half* __restrict__ h0 = g_h16[0][0];
    const __half* __restrict__ h1 = g_h16[0][1];
    const float* __restrict__ wr = fc1_w + (size_t)r * (2 * kH);

    float s = 0.f;
    #pragma unroll 4
    for (int i = 0; i < 32; i++) {
        int k = i * 128 + lane * 4;
        float4 wv = *(const float4*)(wr + k);
        const __half* hs = (k < kH) ? (h0 + k) : (h1 + (k - kH));
        uint2 hh = *(const uint2*)hs;
        float2 f0 = __half22float2(*(const __half2*)&hh.x);
        float2 f1 = __half22float2(*(const __half2*)&hh.y);
        s = fmaf(wv.x, f0.x, s); s = fmaf(wv.y, f0.y, s);
        s = fmaf(wv.z, f1.x, s); s = fmaf(wv.w, f1.y, s);
    }
    #pragma unroll
    for (int off = 16; off; off >>= 1) s += __shfl_down_sync(0xffffffffu, s, off);
    if (lane == 0) g_act[r] = fmaxf(s + fc1_b[r], 0.f);
}

// ---------------- Phase C2: fc2 + log_softmax ----------------
__global__ void head_fc2(const float* __restrict__ fc2_w, const float* __restrict__ fc2_b,
                         float* __restrict__ out)
{
    __shared__ float logits[3];
    const int g = threadIdx.x >> 5, lane = threadIdx.x & 31;
    float s = 0.f;
    const float* wr = fc2_w + g * 256;
    #pragma unroll
    for (int i = 0; i < 2; i++) {
        int k = lane * 8 + i * 4;
        float4 wv = *(const float4*)(wr + k);
        float4 av = *(const float4*)(g_act + k);
        s = fmaf(wv.x, av.x, s); s = fmaf(wv.y, av.y, s);
        s = fmaf(wv.z, av.z, s); s = fmaf(wv.w, av.w, s);
    }
    #pragma unroll
    for (int off = 16; off; off >>= 1) s += __shfl_down_sync(0xffffffffu, s, off);
    if (lane == 0) logits[g] = s + fc2_b[g];
    __syncthreads();
    if (threadIdx.x == 0) {
        float m = fmaxf(logits[0], fmaxf(logits[1], logits[2]));
        float lse = m + logf(expf(logits[0] - m) + expf(logits[1] - m) + expf(logits[2] - m));
        out[0] = logits[0] - lse;
        out[1] = logits[1] - lse;
        out[2] = logits[2] - lse;
    }
}

// ---------------- launch (gru_seq at my index 3 -> global index 5 for ncu) ----------
extern "C" void kernel_launch(void* const* d_in, const int* in_sizes, int n_in,
                              void* d_out, int out_size)
{
    const float* x1   = (const float*)d_in[0];
    const float* x2   = (const float*)d_in[1];
    const float* Wih1 = (const float*)d_in[2];
    const float* Whh1 = (const float*)d_in[3];
    const float* bih1 = (const float*)d_in[4];
    const float* bhh1 = (const float*)d_in[5];
    const float* Wih2 = (const float*)d_in[6];
    const float* Whh2 = (const float*)d_in[7];
    const float* bih2 = (const float*)d_in[8];
    const float* bhh2 = (const float*)d_in[9];
    const float* fc1w = (const float*)d_in[10];
    const float* fc1b = (const float*)d_in[11];
    const float* fc2w = (const float*)d_in[12];
    const float* fc2b = (const float*)d_in[13];
    float* out = (float*)d_out;

    cudaFuncSetAttribute(gru_seq, cudaFuncAttributeMaxDynamicSharedMemorySize, GRU_SMEM);

    convert_whh_both<<<dim3(kH3 * kH / 2 / 1024, 2), 1024>>>(Whh1, Whh2);     // 0
    convert_misc<<<dim3(kH3 * kD / 2 / 1024, 2, 2), 1024>>>(Wih1, Wih2, x1, x2); // 1

    dim3 gA(kH3 / GBN, kT / GBM, 2);
    gemm_xp16<<<gA, 256>>>(bih1, bih2);                                       // 2 (resets g_ctr)

    gru_seq<<<128, GRU_THREADS, GRU_SMEM>>>(bhh1, bhh2);                      // 3 (profiled)

    head_fc1<<<32, 256>>>(fc1w, fc1b);                                        // 4
    head_fc2<<<1, 96>>>(fc2w, fc2b, out);                                     // 5
}

// round 8
// speedup vs baseline: 1.7391x; 1.7391x over previous
#include <cuda_runtime.h>
#include <cuda_fp16.h>
#include <math.h>
#include <stdint.h>

// Problem dims
constexpr int kT  = 4096;   // timesteps
constexpr int kD  = 1024;   // input dim
constexpr int kH  = 2048;   // hidden
constexpr int kH3 = 3 * kH; // 6144

// GRU kernel: 148 blocks (74 per GRU), 1024 threads.
// Block owns nj = 28 (blocks 0..49) or 27 (blocks 50..73) hidden units -> R = 3*nj rows.
// Last 32 rows live in registers (exactly 1 row per warp = 32 regs/thread, uniform).
// First S = R-32 rows (49..52) live in smem.
constexpr int NBLK      = 74;      // blocks per GRU
constexpr int NBIG      = 50;      // blocks with 28 j
constexpr int SMAX      = 52;      // max smem rows
constexpr int GRU_SMEM  = kH * 2 + SMAX * kH * 2 + 96 * 4;  // 4096 + 212992 + 384 = 217472

// -------- scratch (static device globals; no allocation allowed) --------
__device__ float  g_xp[2][(size_t)kT * kH3];    // input projections (fp32)
__device__ __half g_w16[2][(size_t)kH3 * kH];   // fp16 W_hh
__device__ __half g_wih16[2][(size_t)kH3 * kD]; // fp16 W_ih
__device__ __half g_x16[2][(size_t)kT * kD];    // fp16 x
__device__ __align__(16) __half g_h16[2][2][kH]; // ping-pong hidden state [buf][gru][H]
__device__ float  g_act[256];                   // fc1 activations
__device__ unsigned g_ctr[2];                   // monotonic barrier counters (reset by gemm)

// ---------------- monotonic-counter grid barrier (74 blocks per GRU) ----------------
__device__ __forceinline__ void bar_sync(int gru, unsigned target)
{
    __syncthreads();
    if (threadIdx.x == 0) {
        __threadfence();                       // release this block's writes
        atomicAdd(&g_ctr[gru], 1u);
        while (*(volatile unsigned*)&g_ctr[gru] < target) {}
        __threadfence();                       // acquire others' writes
    }
    __syncthreads();
}

// ---------------- conversions (2 launches so gru_seq stays at my index 3) ------------
__global__ void convert_whh_both(const float* __restrict__ W1, const float* __restrict__ W2)
{
    const size_t i = (size_t)blockIdx.x * blockDim.x + threadIdx.x;   // kH3*kH/2
    const float2* src = (const float2*)(blockIdx.y ? W2 : W1);
    float2 v = src[i];
    ((__half2*)g_w16[blockIdx.y])[i] = __floats2half2_rn(v.x, v.y);
}
__global__ void convert_misc(const float* __restrict__ Wih1, const float* __restrict__ Wih2,
                             const float* __restrict__ x1,   const float* __restrict__ x2)
{
    const size_t i = (size_t)blockIdx.x * blockDim.x + threadIdx.x;
    const int gru = blockIdx.y;
    if (blockIdx.z == 0) {                      // W_ih: kH3*kD/2 elements
        const float2* src = (const float2*)(gru ? Wih2 : Wih1);
        float2 v = src[i];
        ((__half2*)g_wih16[gru])[i] = __floats2half2_rn(v.x, v.y);
    } else {                                    // x: kT*kD/2 elements (guard)
        if (i >= (size_t)kT * kD / 2) return;
        const float2* src = (const float2*)(gru ? x2 : x1);
        float2 v = src[i];
        ((__half2*)g_x16[gru])[i] = __floats2half2_rn(v.x, v.y);
    }
}

// ---------------- Phase A: xp = x @ W_ih^T + b_ih  (fp16 HFMA2) ----------------
constexpr int GBM = 128, GBN = 64, GBK = 32;

__global__ void __launch_bounds__(256, 2) gemm_xp16(
    const float* __restrict__ bih1, const float* __restrict__ bih2)
{
    // reset gru barrier counters for this graph replay (runs before gru_seq in-stream)
    if (blockIdx.x == 0 && blockIdx.y == 0 && blockIdx.z == 0 && threadIdx.x == 0) {
        g_ctr[0] = 0; g_ctr[1] = 0;
    }

    const int gru = blockIdx.z;
    const __half* __restrict__ X = g_x16[gru];
    const __half* __restrict__ W = g_wih16[gru];
    const float*  __restrict__ b = gru ? bih2 : bih1;
    float* __restrict__ xp = g_xp[gru];

    __shared__ __half2 As[GBK / 2][GBM + 1];
    __shared__ __half2 Bs[GBK / 2][GBN + 1];

    const int tid = threadIdx.x;
    const int tx = tid & 15, ty = tid >> 4;
    const int t0 = blockIdx.y * GBM;
    const int j0 = blockIdx.x * GBN;

    float acc[8][4] = {};

    for (int k0 = 0; k0 < kD; k0 += GBK) {
        #pragma unroll
        for (int r = 0; r < 2; r++) {
            int i = tid + r * 256;
            int t = i >> 2;
            int kc = (i & 3) * 8;
            uint4 v = *(const uint4*)(X + (size_t)(t0 + t) * kD + k0 + kc);
            const __half2* hv = (const __half2*)&v;
            int k2b = kc >> 1;
            As[k2b + 0][t] = hv[0]; As[k2b + 1][t] = hv[1];
            As[k2b + 2][t] = hv[2]; As[k2b + 3][t] = hv[3];
        }
        {
            int j = tid >> 2;
            int kc = (tid & 3) * 8;
            uint4 v = *(const uint4*)(W + (size_t)(j0 + j) * kD + k0 + kc);
            const __half2* hv = (const __half2*)&v;
            int k2b = kc >> 1;
            Bs[k2b + 0][j] = hv[0]; Bs[k2b + 1][j] = hv[1];
            Bs[k2b + 2][j] = hv[2]; Bs[k2b + 3][j] = hv[3];
        }
        __syncthreads();

        __half2 hz = __float2half2_rn(0.f);
        __half2 hacc[8][4];
        #pragma unroll
        for (int i = 0; i < 8; i++)
            #pragma unroll
            for (int l = 0; l < 4; l++) hacc[i][l] = hz;

        #pragma unroll
        for (int k2 = 0; k2 < GBK / 2; k2++) {
            __half2 a[8], bb[4];
            #pragma unroll
            for (int i = 0; i < 8; i++) a[i] = As[k2][ty * 8 + i];
            #pragma unroll
            for (int l = 0; l < 4; l++) bb[l] = Bs[k2][tx * 4 + l];
            #pragma unroll
            for (int i = 0; i < 8; i++)
                #pragma unroll
                for (int l = 0; l < 4; l++)
                    hacc[i][l] = __hfma2(a[i], bb[l], hacc[i][l]);
        }
        #pragma unroll
        for (int i = 0; i < 8; i++)
            #pragma unroll
            for (int l = 0; l < 4; l++) {
                float2 f = __half22float2(hacc[i][l]);
                acc[i][l] += f.x + f.y;
            }
        __syncthreads();
    }

    const int jj = j0 + tx * 4;
    float4 bv = *(const float4*)(b + jj);
    #pragma unroll
    for (int i = 0; i < 8; i++) {
        float4 v = make_float4(acc[i][0] + bv.x, acc[i][1] + bv.y,
                               acc[i][2] + bv.z, acc[i][3] + bv.w);
        __stcs((float4*)(xp + (size_t)(t0 + ty * 8 + i) * kH3 + jj), v);
    }
}

// ---------------- 8-half dot (fp16 mul-acc, fp32 flush) ----------------
__device__ __forceinline__ float dot8(uint4 wv, uint4 hh)
{
    __half2 t = __hmul2(*(const __half2*)&wv.x, *(const __half2*)&hh.x);
    t = __hfma2(*(const __half2*)&wv.y, *(const __half2*)&hh.y, t);
    t = __hfma2(*(const __half2*)&wv.z, *(const __half2*)&hh.z, t);
    t = __hfma2(*(const __half2*)&wv.w, *(const __half2*)&hh.w, t);
    float2 f = __half22float2(t);
    return f.x + f.y;
}

// ---------------- Phase B: persistent GRU, ALL weights on-chip, no spills ------------
// 148 blocks x 1024 threads. Rows lr = lj*3 + gate, lr < S in smem, S..R-1 in registers
// (reg row of warp w is lr = S + w: exactly 32 regs/thread of weights, uniform).
// Warp w also processes smem rows w and (32+w if < S). Warp 31 does the gate math.
__global__ void __launch_bounds__(1024, 1) gru_seq(
    const float* __restrict__ bhh1, const float* __restrict__ bhh2)
{
    extern __shared__ unsigned char smem_raw[];
    __half* sh_h  = (__half*)smem_raw;                          // 2048 halves
    __half* sh_w  = (__half*)(smem_raw + kH * 2);               // S rows x 2048 halves
    float*  s_pre = (float*)(smem_raw + kH * 2 + SMAX * kH * 2); // up to 84 row sums

    const int blk = blockIdx.x;            // 0..147
    const int gru = (blk >= NBLK) ? 1 : 0;
    const int b   = blk - gru * NBLK;      // 0..73
    const int nj    = (b < NBIG) ? 28 : 27;
    const int jbase = (b < NBIG) ? b * 28 : NBIG * 28 + (b - NBIG) * 27;
    const int R = 3 * nj;                  // 84 or 81
    const int S = R - 32;                  // 52 or 49

    const float*  __restrict__ bhh = gru ? bhh2 : bhh1;
    const float*  __restrict__ xp  = g_xp[gru];
    const __half* __restrict__ W16 = g_w16[gru];

    const int tid = threadIdx.x;
    const int w = tid >> 5, lane = tid & 31;

    // ---- fill smem rows lr < S ----
    for (int idx = tid; idx < S * 256; idx += 1024) {
        int lr = idx >> 8, u = idx & 255;
        int lj = lr / 3, g = lr - 3 * lj;
        ((uint4*)sh_w)[idx] =
            ((const uint4*)(W16 + ((size_t)g * kH + jbase + lj) * kH))[u];
    }

    // ---- preload this warp's single register row (lr = S + w) ----
    uint4 wreg[8];
    {
        int lr = S + w;
        int lj = lr / 3, g = lr - 3 * lj;
        const uint4* p = (const uint4*)(W16 + ((size_t)g * kH + jbase + lj) * kH);
        #pragma unroll
        for (int u = 0; u < 8; u++) wreg[u] = __ldcg(p + u * 32 + lane);
    }

    if (tid < nj) g_h16[0][gru][jbase + tid] = __float2half(0.f);

    // gate math: warp 31, lanes 0..nj-1
    const bool is_gate = (w == 31) && (lane < nj);
    const int jg = jbase + lane;
    float br = 0.f, bz = 0.f, bn = 0.f, h_prev = 0.f;
    if (is_gate) { br = bhh[jg]; bz = bhh[kH + jg]; bn = bhh[2 * kH + jg]; }

    const bool has2 = (32 + w) < S;
    const uint4* p0 = (const uint4*)sh_w + w * 256;
    const uint4* p1 = (const uint4*)sh_w + (32 + w) * 256;
    const uint4* hv = (const uint4*)sh_h;

    bar_sync(gru, NBLK);   // covers smem fill + h0 init across blocks

    for (int t = 0; t < kT; t++) {
        const int cur = t & 1, nxt = cur ^ 1;

        // prefetch xp early (consumed after the dot phase)
        float xr = 0.f, xz = 0.f, xn = 0.f;
        if (is_gate) {
            const float* xpt = xp + (size_t)t * kH3;
            xr = __ldcs(xpt + jg);
            xz = __ldcs(xpt + kH + jg);
            xn = __ldcs(xpt + 2 * kH + jg);
        }

        // stage h (256 x uint4)
        if (tid < 256)
            ((uint4*)sh_h)[tid] = ((const uint4*)g_h16[cur][gru])[tid];
        __syncthreads();

        float a0 = 0.f, a1 = 0.f, a2 = 0.f;
        #pragma unroll
        for (int c = 0; c < 8; c++) {
            uint4 hh = hv[c * 32 + lane];
            a0 += dot8(p0[c * 32 + lane], hh);
            if (has2) a1 += dot8(p1[c * 32 + lane], hh);
            a2 += dot8(wreg[c], hh);
        }

        // butterfly reduce
        #pragma unroll
        for (int off = 16; off; off >>= 1) {
            a0 += __shfl_xor_sync(0xffffffffu, a0, off);
            a1 += __shfl_xor_sync(0xffffffffu, a1, off);
            a2 += __shfl_xor_sync(0xffffffffu, a2, off);
        }

        if (lane == 0) {
            s_pre[w] = a0;
            if (has2) s_pre[32 + w] = a1;
            s_pre[S + w] = a2;
        }
        __syncthreads();

        if (is_gate) {
            int lj = lane;
            float hr = s_pre[3 * lj + 0] + br;
            float hz = s_pre[3 * lj + 1] + bz;
            float hn = s_pre[3 * lj + 2] + bn;
            float r = 1.f / (1.f + expf(-(xr + hr)));
            float z = 1.f / (1.f + expf(-(xz + hz)));
            float n = tanhf(xn + r * hn);
            float hnew = (1.f - z) * n + z * h_prev;
            h_prev = hnew;
            g_h16[nxt][gru][jg] = __float2half(hnew);
        }

        bar_sync(gru, (unsigned)NBLK * (t + 2));
    }
    // final h in g_h16[0] (t=4095: cur=1 -> nxt=0)
}

// ---------------- Phase C1: fc1 (parallel over 32 blocks) ----------------
__global__ void head_fc1(const float* __restrict__ fc1_w, const float* __restrict__ fc1_b)
{
    const int r = blockIdx.x * 8 + (threadIdx.x >> 5);
    const int lane = threadIdx.x & 31;
    const __half* __restrict__ h0 = g_h16[0][0];
    const __half* __restrict__ h1 = g_h16[0][1];
    const float* __restrict__ wr = fc1_w + (size_t)r * (2 * kH);

    float s = 0.f;
    #pragma unroll 4
    for (int i = 0; i < 32; i++) {
        int k = i * 128 + lane * 4;
        float4 wv = *(const float4*)(wr + k);
        const __half* hs = (k < kH) ? (h0 + k) : (h1 + (k - kH));
        uint2 hh = *(const uint2*)hs;
        float2 f0 = __half22float2(*(const __half2*)&hh.x);
        float2 f1 = __half22float2(*(const __half2*)&hh.y);
        s = fmaf(wv.x, f0.x, s); s = fmaf(wv.y, f0.y, s);
        s = fmaf(wv.z, f1.x, s); s = fmaf(wv.w, f1.y, s);
    }
    #pragma unroll
    for (int off = 16; off; off >>= 1) s += __shfl_down_sync(0xffffffffu, s, off);
    if (lane == 0) g_act[r] = fmaxf(s + fc1_b[r], 0.f);
}

// ---------------- Phase C2: fc2 + log_softmax ----------------
__global__ void head_fc2(const float* __restrict__ fc2_w, const float* __restrict__ fc2_b,
                         float* __restrict__ out)
{
    __shared__ float logits[3];
    const int g = threadIdx.x >> 5, lane = threadIdx.x & 31;
    float s = 0.f;
    const float* wr = fc2_w + g * 256;
    #pragma unroll
    for (int i = 0; i < 2; i++) {
        int k = lane * 8 + i * 4;
        float4 wv = *(const float4*)(wr + k);
        float4 av = *(const float4*)(g_act + k);
        s = fmaf(wv.x, av.x, s); s = fmaf(wv.y, av.y, s);
        s = fmaf(wv.z, av.z, s); s = fmaf(wv.w, av.w, s);
    }
    #pragma unroll
    for (int off = 16; off; off >>= 1) s += __shfl_down_sync(0xffffffffu, s, off);
    if (lane == 0) logits[g] = s + fc2_b[g];
    __syncthreads();
    if (threadIdx.x == 0) {
        float m = fmaxf(logits[0], fmaxf(logits[1], logits[2]));
        float lse = m + logf(expf(logits[0] - m) + expf(logits[1] - m) + expf(logits[2] - m));
        out[0] = logits[0] - lse;
        out[1] = logits[1] - lse;
        out[2] = logits[2] - lse;
    }
}

// ---------------- launch (gru_seq at my index 3 for ncu capture) ----------------
extern "C" void kernel_launch(void* const* d_in, const int* in_sizes, int n_in,
                              void* d_out, int out_size)
{
    const float* x1   = (const float*)d_in[0];
    const float* x2   = (const float*)d_in[1];
    const float* Wih1 = (const float*)d_in[2];
    const float* Whh1 = (const float*)d_in[3];
    const float* bih1 = (const float*)d_in[4];
    const float* bhh1 = (const float*)d_in[5];
    const float* Wih2 = (const float*)d_in[6];
    const float* Whh2 = (const float*)d_in[7];
    const float* bih2 = (const float*)d_in[8];
    const float* bhh2 = (const float*)d_in[9];
    const float* fc1w = (const float*)d_in[10];
    const float* fc1b = (const float*)d_in[11];
    const float* fc2w = (const float*)d_in[12];
    const float* fc2b = (const float*)d_in[13];
    float* out = (float*)d_out;

    cudaFuncSetAttribute(gru_seq, cudaFuncAttributeMaxDynamicSharedMemorySize, GRU_SMEM);

    convert_whh_both<<<dim3(kH3 * kH / 2 / 1024, 2), 1024>>>(Whh1, Whh2);        // 0
    convert_misc<<<dim3(kH3 * kD / 2 / 1024, 2, 2), 1024>>>(Wih1, Wih2, x1, x2); // 1

    dim3 gA(kH3 / GBN, kT / GBM, 2);
    gemm_xp16<<<gA, 256>>>(bih1, bih2);                                          // 2 (resets g_ctr)

    gru_seq<<<2 * NBLK, 1024, GRU_SMEM>>>(bhh1, bhh2);                           // 3 (profiled)

    head_fc1<<<32, 256>>>(fc1w, fc1b);                                           // 4
    head_fc2<<<1, 96>>>(fc2w, fc2b, out);                                        // 5
}